// round 14
// baseline (speedup 1.0000x reference)
#include <cuda_runtime.h>
#include <cuda_fp16.h>

#define NN 100000
#define DD 64
#define HD 32   // half2 elements per node row
#define EE 1200000
#define SCAN_CHUNK 1024
#define NBLK_SCAN ((NN + SCAN_CHUNK - 1) / SCAN_CHUNK)  // 98

// ---------------- scratch (static device globals; zero-init at module load) ----------------
__device__ int     g_deg[NN];      // col-degree        (zeroed by cleanup_k each call)
__device__ int     g_cnt[NN];      // row counts        (zeroed by cleanup_k each call)
__device__ int     g_rowptr[NN];   // exclusive scan of g_cnt
__device__ int     g_cursor[NN];   // placement cursors (pre-seeded by scan)
__device__ float   g_invsq[NN];    // rsqrt(max(deg,1))
__device__ int     g_aggr[NBLK_SCAN];          // per-block aggregates
__device__ volatile int g_ready[NBLK_SCAN];    // publish flags (zeroed by cleanup_k)
__device__ int     g_col[EE];      // col only, sorted by row
__device__ __half2 g_x0[NN * HD];  // pre-scaled features: invsq[node]*x[node]
__device__ __half2 g_x1[NN * HD];

// ---------------- per-block dtype self-detection ----------------
__device__ __forceinline__ int block_detect_is64(const unsigned* w) {
    unsigned s = w[((threadIdx.x & 255) << 1) | 1];
    return __syncthreads_and(s == 0u);
}

__device__ __forceinline__ int edge_val(const void* ei, long long idx, int is64) {
    if (is64) return (int)((const long long*)ei)[idx];
    return ((const int*)ei)[idx];
}

// ---------------- launch 0: histograms (col-degree + row counts) ----------------
__global__ void hist_k(const void* __restrict__ ei) {
    int is64 = block_detect_is64((const unsigned*)ei);
    int e = blockIdx.x * blockDim.x + threadIdx.x;
    if (e >= EE) return;
    int r = edge_val(ei, e, is64);
    int c = edge_val(ei, (long long)EE + e, is64);
    atomicAdd(&g_deg[c], 1);
    atomicAdd(&g_cnt[r], 1);
}

// ---------------- launch 1: fused single-pass scan + invsq + cursor + x0 scale ----
__global__ void scanscale_k(const float* __restrict__ emb) {
    __shared__ int wsum[32];
    __shared__ int pred[128];
    __shared__ float sinv[SCAN_CHUNK];
    int bid = blockIdx.x;
    int g = bid * SCAN_CHUNK + threadIdx.x;
    int v = (g < NN) ? g_cnt[g] : 0;
    int lane = threadIdx.x & 31, wid = threadIdx.x >> 5;

    int x = v;
#pragma unroll
    for (int off = 1; off < 32; off <<= 1) {
        int t = __shfl_up_sync(0xffffffffu, x, off);
        if (lane >= off) x += t;
    }
    if (lane == 31) wsum[wid] = x;
    __syncthreads();
    if (wid == 0) {
        int s = wsum[lane];
#pragma unroll
        for (int off = 1; off < 32; off <<= 1) {
            int t = __shfl_up_sync(0xffffffffu, s, off);
            if (lane >= off) s += t;
        }
        wsum[lane] = s;
    }
    __syncthreads();
    int incl = x + (wid ? wsum[wid - 1] : 0);

    if (threadIdx.x == SCAN_CHUNK - 1) {
        g_aggr[bid] = incl;
        __threadfence();
        g_ready[bid] = 1;
    }

    if (threadIdx.x < 128) {
        int a = 0;
        if (threadIdx.x < bid) {
            while (g_ready[threadIdx.x] == 0) { }
            __threadfence();
            a = g_aggr[threadIdx.x];
        }
        pred[threadIdx.x] = a;
    }
    __syncthreads();
    if (threadIdx.x < 64) pred[threadIdx.x] += pred[threadIdx.x + 64];
    __syncthreads();
    if (threadIdx.x < 32) {
        int s = pred[threadIdx.x] + pred[threadIdx.x + 32];
#pragma unroll
        for (int m = 16; m; m >>= 1) s += __shfl_xor_sync(0xffffffffu, s, m);
        if (threadIdx.x == 0) pred[0] = s;
    }
    __syncthreads();
    int offset = pred[0];

    float inv = 0.0f;
    if (g < NN) {
        int p = incl - v + offset;
        g_rowptr[g] = p;
        g_cursor[g] = p;
        inv = rsqrtf(fmaxf((float)g_deg[g], 1.0f));
        g_invsq[g] = inv;
    }
    sinv[threadIdx.x] = inv;
    __syncthreads();

    int base = bid * SCAN_CHUNK * HD;
    int limit = min(NN * HD - base, SCAN_CHUNK * HD);
    for (int i = threadIdx.x; i < limit; i += SCAN_CHUNK) {
        float isr = sinv[i >> 5];
        float2 e = ((const float2*)emb)[base + i];
        g_x0[base + i] = __floats2half2_rn(e.x * isr, e.y * isr);
    }
}

// ---------------- launch 2: place edges into CSR (col only) ----------------
__global__ void place_k(const void* __restrict__ ei) {
    int is64 = block_detect_is64((const unsigned*)ei);
    int e = blockIdx.x * blockDim.x + threadIdx.x;
    if (e >= EE) return;
    int r = edge_val(ei, e, is64);
    int c = edge_val(ei, (long long)EE + e, is64);
    int pos = atomicAdd(&g_cursor[r], 1);
    g_col[pos] = c;
}

// ---------------- launches 3-5: fused layer, wide-gather version ----------------
// One warp per node. 4 lane-groups of 8; group g processes edges start+g, start+g+4, ...
// Each lane LDG.128s 16B (8 dims) per edge -> ONE load instruction covers 4 edges.
// Column indices read directly from L1 (uniform per group) -> no SHFL in the loop.
// mode 0: residual from emb;  write x + outf
// mode 1: residual from outf; write x + outf
// mode 2: residual from outf; write outf = (o+v)*0.25 only
__global__ void layer_k(int src, const float* __restrict__ emb,
                        float* __restrict__ outf, int mode) {
    int gw = (blockIdx.x * blockDim.x + threadIdx.x) >> 5;
    int lane = threadIdx.x & 31;
    if (gw >= NN) return;

    const __half2* xin = src ? g_x1 : g_x0;
    __half2* xout = src ? g_x0 : g_x1;

    int start = g_rowptr[gw];
    int end = (gw + 1 < NN) ? g_rowptr[gw + 1] : EE;

    int group = lane >> 3;   // 0..3 : which edge of each 4-edge batch
    int sub = lane & 7;      // 0..7 : which 8-dim slice of the row

    float a0 = 0.f, a1 = 0.f, a2 = 0.f, a3 = 0.f;
    float a4 = 0.f, a5 = 0.f, a6 = 0.f, a7 = 0.f;
    for (int e = start + group; e < end; e += 4) {
        int c = __ldg(&g_col[e]);
        int4 d = __ldg((const int4*)&xin[c * HD + sub * 4]);
        float2 v0 = __half22float2(*(__half2*)&d.x);
        float2 v1 = __half22float2(*(__half2*)&d.y);
        float2 v2 = __half22float2(*(__half2*)&d.z);
        float2 v3 = __half22float2(*(__half2*)&d.w);
        a0 += v0.x;  a1 += v0.y;
        a2 += v1.x;  a3 += v1.y;
        a4 += v2.x;  a5 += v2.y;
        a6 += v3.x;  a7 += v3.y;
    }

    // combine the 4 edge-groups (same dims live in lanes with equal sub)
#pragma unroll
    for (int off = 8; off <= 16; off <<= 1) {
        a0 += __shfl_xor_sync(0xffffffffu, a0, off);
        a1 += __shfl_xor_sync(0xffffffffu, a1, off);
        a2 += __shfl_xor_sync(0xffffffffu, a2, off);
        a3 += __shfl_xor_sync(0xffffffffu, a3, off);
        a4 += __shfl_xor_sync(0xffffffffu, a4, off);
        a5 += __shfl_xor_sync(0xffffffffu, a5, off);
        a6 += __shfl_xor_sync(0xffffffffu, a6, off);
        a7 += __shfl_xor_sync(0xffffffffu, a7, off);
    }

    float isr = g_invsq[gw];
    const float* res = (mode == 0) ? emb : outf;
    int fbase = gw * DD + sub * 8;
    float4 o0 = __ldg((const float4*)&res[fbase]);
    float4 o1 = __ldg((const float4*)&res[fbase + 4]);

    float v0 = a0 * isr + o0.x;
    float v1 = a1 * isr + o0.y;
    float v2 = a2 * isr + o0.z;
    float v3 = a3 * isr + o0.w;
    float v4 = a4 * isr + o1.x;
    float v5 = a5 * isr + o1.y;
    float v6 = a6 * isr + o1.z;
    float v7 = a7 * isr + o1.w;

    float ss = v0 * v0 + v1 * v1 + v2 * v2 + v3 * v3
             + v4 * v4 + v5 * v5 + v6 * v6 + v7 * v7;
    ss += __shfl_xor_sync(0xffffffffu, ss, 1);
    ss += __shfl_xor_sync(0xffffffffu, ss, 2);
    ss += __shfl_xor_sync(0xffffffffu, ss, 4);
    float s = 1.0f / fmaxf(sqrtf(ss), 1e-12f);
    v0 *= s;  v1 *= s;  v2 *= s;  v3 *= s;
    v4 *= s;  v5 *= s;  v6 *= s;  v7 *= s;

    if (group == 0) {
        if (mode == 2) {
            ((float4*)&outf[fbase])[0]     = make_float4((o0.x + v0) * 0.25f, (o0.y + v1) * 0.25f,
                                                         (o0.z + v2) * 0.25f, (o0.w + v3) * 0.25f);
            ((float4*)&outf[fbase + 4])[0] = make_float4((o1.x + v4) * 0.25f, (o1.y + v5) * 0.25f,
                                                         (o1.z + v6) * 0.25f, (o1.w + v7) * 0.25f);
        } else {
            int4 hx;
            __half2 h0 = __floats2half2_rn(v0 * isr, v1 * isr);
            __half2 h1 = __floats2half2_rn(v2 * isr, v3 * isr);
            __half2 h2 = __floats2half2_rn(v4 * isr, v5 * isr);
            __half2 h3 = __floats2half2_rn(v6 * isr, v7 * isr);
            hx.x = *(int*)&h0;  hx.y = *(int*)&h1;
            hx.z = *(int*)&h2;  hx.w = *(int*)&h3;
            *(int4*)&xout[gw * HD + sub * 4] = hx;
            ((float4*)&outf[fbase])[0]     = make_float4(o0.x + v0, o0.y + v1, o0.z + v2, o0.w + v3);
            ((float4*)&outf[fbase + 4])[0] = make_float4(o1.x + v4, o1.y + v5, o1.z + v6, o1.w + v7);
        }
    }
}

// ---------------- launch 6: restore zeroed state for the next call ----------------
__global__ void cleanup_k() {
    int i = blockIdx.x * blockDim.x + threadIdx.x;
    if (i < NN) {
        g_deg[i] = 0;
        g_cnt[i] = 0;
    }
    if (i < NBLK_SCAN) g_ready[i] = 0;
}

// ---------------- launch (kernel launches ONLY) ----------------
extern "C" void kernel_launch(void* const* d_in, const int* in_sizes, int n_in,
                              void* d_out, int out_size) {
    int ei_idx = 0, emb_idx = 1;
    if (in_sizes[0] == NN * DD) { ei_idx = 1; emb_idx = 0; }
    const void* ei = d_in[ei_idx];
    const float* emb = (const float*)d_in[emb_idx];
    float* out = (float*)d_out;

    const int node_blocks = (NN * 32 + 255) / 256;  // 12500

    hist_k<<<(EE + 255) / 256, 256>>>(ei);            // 0
    scanscale_k<<<NBLK_SCAN, SCAN_CHUNK>>>(emb);      // 1
    place_k<<<(EE + 255) / 256, 256>>>(ei);           // 2
    layer_k<<<node_blocks, 256>>>(0, emb, out, 0);    // 3  <- ncu capture slot
    layer_k<<<node_blocks, 256>>>(1, emb, out, 1);    // 4
    layer_k<<<node_blocks, 256>>>(0, emb, out, 2);    // 5
    cleanup_k<<<(NN + 255) / 256, 256>>>();           // 6
}

// round 16
// speedup vs baseline: 1.0413x; 1.0413x over previous
#include <cuda_runtime.h>
#include <cuda_fp16.h>

#define NN 100000
#define DD 64
#define HD 32   // half2 elements per node row
#define EE 1200000
#define EPAD (EE + 8 * NN + 64)   // padded CSR capacity
#define ZCOL (NN * HD)            // dummy column: pre-scaled index of the zero row
#define SCAN_CHUNK 1024
#define NBLK_SCAN ((NN + SCAN_CHUNK - 1) / SCAN_CHUNK)  // 98

// ---------------- scratch (static device globals; zero-init at module load) ----------------
__device__ int     g_deg[NN];        // col-degree   (zeroed by cleanup_k each call)
__device__ int     g_cnt[NN];        // row counts   (zeroed by cleanup_k each call)
__device__ int     g_rowptr[NN + 1]; // padded-CSR row starts (+ total at [NN])
__device__ int     g_cursor[NN];     // placement cursors (pre-seeded by scan)
__device__ float   g_invsq[NN];      // rsqrt(max(deg,1))
__device__ int     g_aggr[NBLK_SCAN];        // per-block aggregates (padded counts)
__device__ volatile int g_ready[NBLK_SCAN];  // publish flags (zeroed by cleanup_k)
__device__ int     g_col[EPAD];      // pre-scaled col index (c*HD), padded rows
__device__ __half2 g_x0[(NN + 1) * HD];  // +1: zero row for padding (never written)
__device__ __half2 g_x1[(NN + 1) * HD];

// ---------------- per-block dtype self-detection ----------------
// Odd 32-bit words of nonneg int64 < 2^31 are all zero; for int32 node ids
// 256 samples all-zero is impossible. Block agrees via __syncthreads_and.
__device__ __forceinline__ int block_detect_is64(const unsigned* w) {
    unsigned s = w[((threadIdx.x & 255) << 1) | 1];
    return __syncthreads_and(s == 0u);
}

__device__ __forceinline__ int edge_val(const void* ei, long long idx, int is64) {
    if (is64) return (int)((const long long*)ei)[idx];
    return ((const int*)ei)[idx];
}

// ---------------- launch 0: histograms (col-degree + row counts) ----------------
__global__ void hist_k(const void* __restrict__ ei) {
    int is64 = block_detect_is64((const unsigned*)ei);
    int e = blockIdx.x * blockDim.x + threadIdx.x;
    if (e >= EE) return;
    int r = edge_val(ei, e, is64);
    int c = edge_val(ei, (long long)EE + e, is64);
    atomicAdd(&g_deg[c], 1);
    atomicAdd(&g_cnt[r], 1);
}

// ---------------- launch 1: fused scan (over PADDED counts) + invsq + cursor
//                  + x0 scale + padding fill ----------------
// Decoupled lookback; 98 blocks co-resident -> polling is deadlock-free.
__global__ void scanscale_k(const float* __restrict__ emb) {
    __shared__ int wsum[32];
    __shared__ int pred[128];
    __shared__ float sinv[SCAN_CHUNK];
    int bid = blockIdx.x;
    int g = bid * SCAN_CHUNK + threadIdx.x;
    int cnt = (g < NN) ? g_cnt[g] : 0;
    int pcnt = (cnt + 7) & ~7;           // padded to multiple of 8
    int lane = threadIdx.x & 31, wid = threadIdx.x >> 5;

    // block-local inclusive scan of padded counts
    int x = pcnt;
#pragma unroll
    for (int off = 1; off < 32; off <<= 1) {
        int t = __shfl_up_sync(0xffffffffu, x, off);
        if (lane >= off) x += t;
    }
    if (lane == 31) wsum[wid] = x;
    __syncthreads();
    if (wid == 0) {
        int s = wsum[lane];
#pragma unroll
        for (int off = 1; off < 32; off <<= 1) {
            int t = __shfl_up_sync(0xffffffffu, s, off);
            if (lane >= off) s += t;
        }
        wsum[lane] = s;
    }
    __syncthreads();
    int incl = x + (wid ? wsum[wid - 1] : 0);

    if (threadIdx.x == SCAN_CHUNK - 1) {
        g_aggr[bid] = incl;
        __threadfence();
        g_ready[bid] = 1;
    }

    if (threadIdx.x < 128) {
        int a = 0;
        if (threadIdx.x < bid) {
            while (g_ready[threadIdx.x] == 0) { }
            __threadfence();
            a = g_aggr[threadIdx.x];
        }
        pred[threadIdx.x] = a;
    }
    __syncthreads();
    if (threadIdx.x < 64) pred[threadIdx.x] += pred[threadIdx.x + 64];
    __syncthreads();
    if (threadIdx.x < 32) {
        int s = pred[threadIdx.x] + pred[threadIdx.x + 32];
#pragma unroll
        for (int m = 16; m; m >>= 1) s += __shfl_xor_sync(0xffffffffu, s, m);
        if (threadIdx.x == 0) pred[0] = s;
    }
    __syncthreads();
    int offset = pred[0];

    float inv = 0.0f;
    if (g < NN) {
        int p = offset + incl - pcnt;   // padded exclusive prefix
        g_rowptr[g] = p;
        g_cursor[g] = p;
        if (g == NN - 1) g_rowptr[NN] = offset + incl;
        inv = rsqrtf(fmaxf((float)g_deg[g], 1.0f));
        g_invsq[g] = inv;
        // fill this row's padding slots with the zero-row column
        for (int q = p + cnt; q < p + pcnt; q++) g_col[q] = ZCOL;
    }
    sinv[threadIdx.x] = inv;
    __syncthreads();

    // scale this block's nodes: x0 = half(invsq * emb)
    int base = bid * SCAN_CHUNK * HD;
    int limit = min(NN * HD - base, SCAN_CHUNK * HD);
    for (int i = threadIdx.x; i < limit; i += SCAN_CHUNK) {
        float isr = sinv[i >> 5];
        float2 e = ((const float2*)emb)[base + i];
        g_x0[base + i] = __floats2half2_rn(e.x * isr, e.y * isr);
    }
}

// ---------------- launch 2: place edges into padded CSR (pre-scaled col) ----------------
__global__ void place_k(const void* __restrict__ ei) {
    int is64 = block_detect_is64((const unsigned*)ei);
    int e = blockIdx.x * blockDim.x + threadIdx.x;
    if (e >= EE) return;
    int r = edge_val(ei, e, is64);
    int c = edge_val(ei, (long long)EE + e, is64);
    int pos = atomicAdd(&g_cursor[r], 1);
    g_col[pos] = c * HD;   // pre-scaled half2 row base
}

// ---------------- launches 3-5: fused layer (padded CSR pull, tail-free x8 loop) ----
// One warp per node; 2 dims per lane. Row length is a multiple of 8 ->
// every inner trip is a full 8-edge unroll: 8 SHFL + 8 LDG + cvt + FADD.
// mode 0: residual from emb;  write x + outf
// mode 1: residual from outf; write x + outf
// mode 2: residual from outf; write outf = (o+v)*0.25 only
__global__ void layer_k(int src, const float* __restrict__ emb,
                        float* __restrict__ outf, int mode) {
    int gw = (blockIdx.x * blockDim.x + threadIdx.x) >> 5;
    int lane = threadIdx.x & 31;
    if (gw >= NN) return;

    const __half2* xin = src ? g_x1 : g_x0;
    __half2* xout = src ? g_x0 : g_x1;

    int start = g_rowptr[gw];
    int end = g_rowptr[gw + 1];

    float ax = 0.0f, ay = 0.0f;
    for (int base = start; base < end; base += 32) {
        int n = min(32, end - base);          // multiple of 8
        int colv = 0;
        if (lane < n) colv = __ldg(&g_col[base + lane]);
        for (int js = 0; js < n; js += 8) {
            int c0 = __shfl_sync(0xffffffffu, colv, js);
            int c1 = __shfl_sync(0xffffffffu, colv, js + 1);
            int c2 = __shfl_sync(0xffffffffu, colv, js + 2);
            int c3 = __shfl_sync(0xffffffffu, colv, js + 3);
            int c4 = __shfl_sync(0xffffffffu, colv, js + 4);
            int c5 = __shfl_sync(0xffffffffu, colv, js + 5);
            int c6 = __shfl_sync(0xffffffffu, colv, js + 6);
            int c7 = __shfl_sync(0xffffffffu, colv, js + 7);
            __half2 h0 = __ldg(&xin[c0 + lane]);
            __half2 h1 = __ldg(&xin[c1 + lane]);
            __half2 h2 = __ldg(&xin[c2 + lane]);
            __half2 h3 = __ldg(&xin[c3 + lane]);
            __half2 h4 = __ldg(&xin[c4 + lane]);
            __half2 h5 = __ldg(&xin[c5 + lane]);
            __half2 h6 = __ldg(&xin[c6 + lane]);
            __half2 h7 = __ldg(&xin[c7 + lane]);
            float2 v0 = __half22float2(h0);
            float2 v1 = __half22float2(h1);
            float2 v2 = __half22float2(h2);
            float2 v3 = __half22float2(h3);
            float2 v4 = __half22float2(h4);
            float2 v5 = __half22float2(h5);
            float2 v6 = __half22float2(h6);
            float2 v7 = __half22float2(h7);
            ax += v0.x + v1.x;  ay += v0.y + v1.y;
            ax += v2.x + v3.x;  ay += v2.y + v3.y;
            ax += v4.x + v5.x;  ay += v4.y + v5.y;
            ax += v6.x + v7.x;  ay += v6.y + v7.y;
        }
    }

    float isr = g_invsq[gw];
    ax *= isr;
    ay *= isr;

    int bidx = gw * HD + lane;
    float2 o;
    if (mode == 0) o = ((const float2*)emb)[bidx];
    else           o = ((const float2*)outf)[bidx];

    float vx = ax + o.x;
    float vy = ay + o.y;
    float ss = vx * vx + vy * vy;
#pragma unroll
    for (int m = 16; m; m >>= 1) ss += __shfl_xor_sync(0xffffffffu, ss, m);
    float s = 1.0f / fmaxf(sqrtf(ss), 1e-12f);
    vx *= s;
    vy *= s;

    if (mode == 2) {
        ((float2*)outf)[bidx] = make_float2((o.x + vx) * 0.25f, (o.y + vy) * 0.25f);
    } else {
        xout[bidx] = __floats2half2_rn(vx * isr, vy * isr);
        ((float2*)outf)[bidx] = make_float2(o.x + vx, o.y + vy);
    }
}

// ---------------- launch 6: restore zeroed state for the next call ----------------
__global__ void cleanup_k() {
    int i = blockIdx.x * blockDim.x + threadIdx.x;
    if (i < NN) {
        g_deg[i] = 0;
        g_cnt[i] = 0;
    }
    if (i < NBLK_SCAN) g_ready[i] = 0;
}

// ---------------- launch (kernel launches ONLY) ----------------
extern "C" void kernel_launch(void* const* d_in, const int* in_sizes, int n_in,
                              void* d_out, int out_size) {
    int ei_idx = 0, emb_idx = 1;
    if (in_sizes[0] == NN * DD) { ei_idx = 1; emb_idx = 0; }
    const void* ei = d_in[ei_idx];
    const float* emb = (const float*)d_in[emb_idx];
    float* out = (float*)d_out;

    const int node_blocks = (NN * 32 + 255) / 256;  // 12500

    hist_k<<<(EE + 255) / 256, 256>>>(ei);            // 0
    scanscale_k<<<NBLK_SCAN, SCAN_CHUNK>>>(emb);      // 1
    place_k<<<(EE + 255) / 256, 256>>>(ei);           // 2
    layer_k<<<node_blocks, 256>>>(0, emb, out, 0);    // 3  <- ncu capture slot
    layer_k<<<node_blocks, 256>>>(1, emb, out, 1);    // 4
    layer_k<<<node_blocks, 256>>>(0, emb, out, 2);    // 5
    cleanup_k<<<(NN + 255) / 256, 256>>>();           // 6
}